// round 14
// baseline (speedup 1.0000x reference)
#include <cuda_runtime.h>

#define C 128
#define G_SEG 1024
#define MAX_N 1000000
#define RPW 16    // rows per warp (contiguous chunk, multiple of 4)

// Scratch (zero-initialized at module load; zero-invariant restored every replay)
static __device__ float g_exps[MAX_N];        // e_i (unnormalized), fully overwritten
static __device__ float g_pool[G_SEG * C];    // unnormalized pooled sums (reset by k_fin)
static __device__ float g_sum;                // softmax denominator (reset by k_fin last block)
static __device__ unsigned int g_fin_count;   // k_fin completion counter (reset by last block)

__device__ __forceinline__ void flush_acc(int seg, int lane, float4& acc) {
    int gc = min(max(seg, 0), G_SEG - 1);
    float* p = g_pool + gc * C + lane * 4;
    atomicAdd(p + 0, acc.x);
    atomicAdd(p + 1, acc.y);
    atomicAdd(p + 2, acc.z);
    atomicAdd(p + 3, acc.w);
    acc = make_float4(0.f, 0.f, 0.f, 0.f);
}

// k_main: single 512 MB pass over x, 4 rows in flight per warp (MLP=4).
// Quad fast-path on sorted batch; fence-free; atomics into g_pool scratch.
__global__ void __launch_bounds__(256) k_main(const float* __restrict__ x,
                                              const float* __restrict__ W,
                                              const float* __restrict__ b,
                                              const int* __restrict__ batch,
                                              int N) {
    const int lane  = threadIdx.x & 31;
    const int gwarp = (blockIdx.x * blockDim.x + threadIdx.x) >> 5;
    const int start = gwarp * RPW;

    float lsum = 0.0f;   // warp-uniform

    if (start < N) {
        const int end = min(start + RPW, N);
        const float4 wv = __ldg(reinterpret_cast<const float4*>(W) + lane);
        const float  bb = __ldg(b);
        const float4* xv4 = reinterpret_cast<const float4*>(x);

        int cur = __ldg(batch + start);
        float4 acc = make_float4(0.f, 0.f, 0.f, 0.f);

        int i = start;
        for (; i + 3 < end; i += 4) {
            // 4 independent loads -> MLP=4 on the big stream
            float4 x0 = __ldg(xv4 + (size_t)(i + 0) * 32 + lane);
            float4 x1 = __ldg(xv4 + (size_t)(i + 1) * 32 + lane);
            float4 x2 = __ldg(xv4 + (size_t)(i + 2) * 32 + lane);
            float4 x3 = __ldg(xv4 + (size_t)(i + 3) * 32 + lane);
            int4   gq = __ldg(reinterpret_cast<const int4*>(batch + i)); // aligned

            float d0 = x0.x*wv.x + x0.y*wv.y + x0.z*wv.z + x0.w*wv.w;
            float d1 = x1.x*wv.x + x1.y*wv.y + x1.z*wv.z + x1.w*wv.w;
            float d2 = x2.x*wv.x + x2.y*wv.y + x2.z*wv.z + x2.w*wv.w;
            float d3 = x3.x*wv.x + x3.y*wv.y + x3.z*wv.z + x3.w*wv.w;

            // interleaved butterflies: 4 independent chains share the latency
            #pragma unroll
            for (int o = 16; o; o >>= 1) {
                d0 += __shfl_xor_sync(0xffffffffu, d0, o);
                d1 += __shfl_xor_sync(0xffffffffu, d1, o);
                d2 += __shfl_xor_sync(0xffffffffu, d2, o);
                d3 += __shfl_xor_sync(0xffffffffu, d3, o);
            }

            float e0 = __expf(d0 + bb);
            float e1 = __expf(d1 + bb);
            float e2 = __expf(d2 + bb);
            float e3 = __expf(d3 + bb);

            if (lane == 0)
                *reinterpret_cast<float4*>(g_exps + i) = make_float4(e0, e1, e2, e3);
            lsum += (e0 + e1) + (e2 + e3);

            if (gq.w == cur) {
                // fast path: whole quad in segment cur (sorted => all equal)
                acc.x = fmaf(e0, x0.x, acc.x); acc.y = fmaf(e0, x0.y, acc.y);
                acc.z = fmaf(e0, x0.z, acc.z); acc.w = fmaf(e0, x0.w, acc.w);
                acc.x = fmaf(e1, x1.x, acc.x); acc.y = fmaf(e1, x1.y, acc.y);
                acc.z = fmaf(e1, x1.z, acc.z); acc.w = fmaf(e1, x1.w, acc.w);
                acc.x = fmaf(e2, x2.x, acc.x); acc.y = fmaf(e2, x2.y, acc.y);
                acc.z = fmaf(e2, x2.z, acc.z); acc.w = fmaf(e2, x2.w, acc.w);
                acc.x = fmaf(e3, x3.x, acc.x); acc.y = fmaf(e3, x3.y, acc.y);
                acc.z = fmaf(e3, x3.z, acc.z); acc.w = fmaf(e3, x3.w, acc.w);
            } else {
                // slow path: at least one boundary inside the quad
                if (gq.x != cur) { flush_acc(cur, lane, acc); cur = gq.x; }
                acc.x = fmaf(e0, x0.x, acc.x); acc.y = fmaf(e0, x0.y, acc.y);
                acc.z = fmaf(e0, x0.z, acc.z); acc.w = fmaf(e0, x0.w, acc.w);

                if (gq.y != cur) { flush_acc(cur, lane, acc); cur = gq.y; }
                acc.x = fmaf(e1, x1.x, acc.x); acc.y = fmaf(e1, x1.y, acc.y);
                acc.z = fmaf(e1, x1.z, acc.z); acc.w = fmaf(e1, x1.w, acc.w);

                if (gq.z != cur) { flush_acc(cur, lane, acc); cur = gq.z; }
                acc.x = fmaf(e2, x2.x, acc.x); acc.y = fmaf(e2, x2.y, acc.y);
                acc.z = fmaf(e2, x2.z, acc.z); acc.w = fmaf(e2, x2.w, acc.w);

                if (gq.w != cur) { flush_acc(cur, lane, acc); cur = gq.w; }
                acc.x = fmaf(e3, x3.x, acc.x); acc.y = fmaf(e3, x3.y, acc.y);
                acc.z = fmaf(e3, x3.z, acc.z); acc.w = fmaf(e3, x3.w, acc.w);
            }
        }

        // generic tail (unused when chunk length % 4 == 0)
        for (; i < end; i++) {
            float4 xv = __ldg(xv4 + (size_t)i * 32 + lane);
            int g = __ldg(batch + i);
            float dd = xv.x*wv.x + xv.y*wv.y + xv.z*wv.z + xv.w*wv.w;
            #pragma unroll
            for (int o = 16; o; o >>= 1) dd += __shfl_xor_sync(0xffffffffu, dd, o);
            float ee = __expf(dd + bb);
            if (lane == 0) g_exps[i] = ee;
            lsum += ee;
            if (g != cur) { flush_acc(cur, lane, acc); cur = g; }
            acc.x = fmaf(ee, xv.x, acc.x); acc.y = fmaf(ee, xv.y, acc.y);
            acc.z = fmaf(ee, xv.z, acc.z); acc.w = fmaf(ee, xv.w, acc.w);
        }

        flush_acc(cur, lane, acc);
    }

    // block-level reduction of per-warp sums into g_sum (no fences)
    __shared__ float s_red[8];
    if (lane == 0) s_red[threadIdx.x >> 5] = lsum;
    __syncthreads();
    if (threadIdx.x == 0) {
        float s = 0.0f;
        #pragma unroll
        for (int w = 0; w < 8; w++) s += s_red[w];
        atomicAdd(&g_sum, s);
    }
}

// k_fin: direct-indexed, one float4 op per thread (the measured-best R12 form).
//   idx < N4          : alpha[idx] = e[idx] * inv
//   N4 <= idx < N4+P4 : pooled = g_pool*inv, g_pool reset
// Fence-free g_sum reset via last-block ticket (entry-read + __syncthreads).
__global__ void __launch_bounds__(256) k_fin(float* __restrict__ pooled,
                                             float* __restrict__ alpha, int N4) {
    const float inv = 1.0f / g_sum;     // read before any reset can happen
    __syncthreads();                    // all threads in this block have read

    const int idx = blockIdx.x * blockDim.x + threadIdx.x;
    const int P4 = (G_SEG * C) / 4;

    if (idx < N4) {
        float4 e = reinterpret_cast<const float4*>(g_exps)[idx];
        reinterpret_cast<float4*>(alpha)[idx] =
            make_float4(e.x * inv, e.y * inv, e.z * inv, e.w * inv);
    } else if (idx < N4 + P4) {
        int j = idx - N4;
        float4 v = reinterpret_cast<float4*>(g_pool)[j];
        reinterpret_cast<float4*>(pooled)[j] =
            make_float4(v.x * inv, v.y * inv, v.z * inv, v.w * inv);
        reinterpret_cast<float4*>(g_pool)[j] = make_float4(0.f, 0.f, 0.f, 0.f);
    }

    if (threadIdx.x == 0) {
        unsigned int t = atomicAdd(&g_fin_count, 1u);
        if (t == gridDim.x - 1) {
            g_sum = 0.0f;
            g_fin_count = 0u;
        }
    }
}

extern "C" void kernel_launch(void* const* d_in, const int* in_sizes, int n_in,
                              void* d_out, int out_size) {
    // Defensive input mapping by element counts: x: N*C, W: C, b: 1, batch: N
    const float* x = nullptr;
    const float* W = nullptr;
    const float* b = nullptr;
    const int*   batch = nullptr;
    int N = 0;
    {
        int xi = 0;
        for (int i = 1; i < n_in; i++) if (in_sizes[i] > in_sizes[xi]) xi = i;
        x = (const float*)d_in[xi];
        N = in_sizes[xi] / C;
        for (int i = 0; i < n_in; i++) {
            if (i == xi) continue;
            if (in_sizes[i] == C)      W = (const float*)d_in[i];
            else if (in_sizes[i] == 1) b = (const float*)d_in[i];
            else if (in_sizes[i] == N) batch = (const int*)d_in[i];
        }
    }

    float* pooled = (float*)d_out;             // [G_SEG, C]
    float* alpha  = (float*)d_out + G_SEG * C; // [N]

    int nwarps  = (N + RPW - 1) / RPW;
    int nblocks = (nwarps + 7) / 8;            // 8 warps (256 thr) per block
    k_main<<<nblocks, 256>>>(x, W, b, batch, N);

    int N4  = N / 4;
    int tot = N4 + (G_SEG * C) / 4;
    k_fin<<<(tot + 255) / 256, 256>>>(pooled, alpha, N4);
}

// round 15
// speedup vs baseline: 1.0946x; 1.0946x over previous
#include <cuda_runtime.h>

#define C 128
#define G_SEG 1024
#define MAX_N 1000000
#define RPW 32    // rows per warp — measured minimum of the granularity curve
                  // (128/64/32/16 -> ~93.3 / ~92.9 / 90.8 / 98.9 us)

// Scratch (zero-initialized at module load; zero-invariant restored every replay)
static __device__ float g_exps[MAX_N];        // e_i (unnormalized), fully overwritten
static __device__ float g_pool[G_SEG * C];    // unnormalized pooled sums (reset by k_fin)
static __device__ float g_sum;                // softmax denominator (reset by k_fin last block)
static __device__ unsigned int g_fin_count;   // k_fin completion counter (reset by last block)

__device__ __forceinline__ void flush_acc(int seg, int lane, float4& acc) {
    int gc = min(max(seg, 0), G_SEG - 1);
    float* p = g_pool + gc * C + lane * 4;
    atomicAdd(p + 0, acc.x);
    atomicAdd(p + 1, acc.y);
    atomicAdd(p + 2, acc.z);
    atomicAdd(p + 3, acc.w);
    acc = make_float4(0.f, 0.f, 0.f, 0.f);
}

// k_main: single 512 MB pass over x, 4 rows in flight per warp (MLP=4).
// Quad fast-path on sorted batch; fence-free; atomics into g_pool scratch.
__global__ void __launch_bounds__(256) k_main(const float* __restrict__ x,
                                              const float* __restrict__ W,
                                              const float* __restrict__ b,
                                              const int* __restrict__ batch,
                                              int N) {
    const int lane  = threadIdx.x & 31;
    const int gwarp = (blockIdx.x * blockDim.x + threadIdx.x) >> 5;
    const int start = gwarp * RPW;

    float lsum = 0.0f;   // warp-uniform

    if (start < N) {
        const int end = min(start + RPW, N);
        const float4 wv = __ldg(reinterpret_cast<const float4*>(W) + lane);
        const float  bb = __ldg(b);
        const float4* xv4 = reinterpret_cast<const float4*>(x);

        int cur = __ldg(batch + start);
        float4 acc = make_float4(0.f, 0.f, 0.f, 0.f);

        int i = start;
        for (; i + 3 < end; i += 4) {
            // 4 independent loads -> MLP=4 on the big stream
            float4 x0 = __ldg(xv4 + (size_t)(i + 0) * 32 + lane);
            float4 x1 = __ldg(xv4 + (size_t)(i + 1) * 32 + lane);
            float4 x2 = __ldg(xv4 + (size_t)(i + 2) * 32 + lane);
            float4 x3 = __ldg(xv4 + (size_t)(i + 3) * 32 + lane);
            int4   gq = __ldg(reinterpret_cast<const int4*>(batch + i)); // aligned

            float d0 = x0.x*wv.x + x0.y*wv.y + x0.z*wv.z + x0.w*wv.w;
            float d1 = x1.x*wv.x + x1.y*wv.y + x1.z*wv.z + x1.w*wv.w;
            float d2 = x2.x*wv.x + x2.y*wv.y + x2.z*wv.z + x2.w*wv.w;
            float d3 = x3.x*wv.x + x3.y*wv.y + x3.z*wv.z + x3.w*wv.w;

            // interleaved butterflies: 4 independent chains share the latency
            #pragma unroll
            for (int o = 16; o; o >>= 1) {
                d0 += __shfl_xor_sync(0xffffffffu, d0, o);
                d1 += __shfl_xor_sync(0xffffffffu, d1, o);
                d2 += __shfl_xor_sync(0xffffffffu, d2, o);
                d3 += __shfl_xor_sync(0xffffffffu, d3, o);
            }

            float e0 = __expf(d0 + bb);
            float e1 = __expf(d1 + bb);
            float e2 = __expf(d2 + bb);
            float e3 = __expf(d3 + bb);

            if (lane == 0)
                *reinterpret_cast<float4*>(g_exps + i) = make_float4(e0, e1, e2, e3);
            lsum += (e0 + e1) + (e2 + e3);

            if (gq.w == cur) {
                // fast path: whole quad in segment cur (sorted => all equal)
                acc.x = fmaf(e0, x0.x, acc.x); acc.y = fmaf(e0, x0.y, acc.y);
                acc.z = fmaf(e0, x0.z, acc.z); acc.w = fmaf(e0, x0.w, acc.w);
                acc.x = fmaf(e1, x1.x, acc.x); acc.y = fmaf(e1, x1.y, acc.y);
                acc.z = fmaf(e1, x1.z, acc.z); acc.w = fmaf(e1, x1.w, acc.w);
                acc.x = fmaf(e2, x2.x, acc.x); acc.y = fmaf(e2, x2.y, acc.y);
                acc.z = fmaf(e2, x2.z, acc.z); acc.w = fmaf(e2, x2.w, acc.w);
                acc.x = fmaf(e3, x3.x, acc.x); acc.y = fmaf(e3, x3.y, acc.y);
                acc.z = fmaf(e3, x3.z, acc.z); acc.w = fmaf(e3, x3.w, acc.w);
            } else {
                // slow path: at least one boundary inside the quad
                if (gq.x != cur) { flush_acc(cur, lane, acc); cur = gq.x; }
                acc.x = fmaf(e0, x0.x, acc.x); acc.y = fmaf(e0, x0.y, acc.y);
                acc.z = fmaf(e0, x0.z, acc.z); acc.w = fmaf(e0, x0.w, acc.w);

                if (gq.y != cur) { flush_acc(cur, lane, acc); cur = gq.y; }
                acc.x = fmaf(e1, x1.x, acc.x); acc.y = fmaf(e1, x1.y, acc.y);
                acc.z = fmaf(e1, x1.z, acc.z); acc.w = fmaf(e1, x1.w, acc.w);

                if (gq.z != cur) { flush_acc(cur, lane, acc); cur = gq.z; }
                acc.x = fmaf(e2, x2.x, acc.x); acc.y = fmaf(e2, x2.y, acc.y);
                acc.z = fmaf(e2, x2.z, acc.z); acc.w = fmaf(e2, x2.w, acc.w);

                if (gq.w != cur) { flush_acc(cur, lane, acc); cur = gq.w; }
                acc.x = fmaf(e3, x3.x, acc.x); acc.y = fmaf(e3, x3.y, acc.y);
                acc.z = fmaf(e3, x3.z, acc.z); acc.w = fmaf(e3, x3.w, acc.w);
            }
        }

        // generic tail (unused when chunk length % 4 == 0)
        for (; i < end; i++) {
            float4 xv = __ldg(xv4 + (size_t)i * 32 + lane);
            int g = __ldg(batch + i);
            float dd = xv.x*wv.x + xv.y*wv.y + xv.z*wv.z + xv.w*wv.w;
            #pragma unroll
            for (int o = 16; o; o >>= 1) dd += __shfl_xor_sync(0xffffffffu, dd, o);
            float ee = __expf(dd + bb);
            if (lane == 0) g_exps[i] = ee;
            lsum += ee;
            if (g != cur) { flush_acc(cur, lane, acc); cur = g; }
            acc.x = fmaf(ee, xv.x, acc.x); acc.y = fmaf(ee, xv.y, acc.y);
            acc.z = fmaf(ee, xv.z, acc.z); acc.w = fmaf(ee, xv.w, acc.w);
        }

        flush_acc(cur, lane, acc);
    }

    // block-level reduction of per-warp sums into g_sum (no fences)
    __shared__ float s_red[8];
    if (lane == 0) s_red[threadIdx.x >> 5] = lsum;
    __syncthreads();
    if (threadIdx.x == 0) {
        float s = 0.0f;
        #pragma unroll
        for (int w = 0; w < 8; w++) s += s_red[w];
        atomicAdd(&g_sum, s);
    }
}

// k_fin: direct-indexed, one float4 op per thread (measured-best form).
//   idx < N4          : alpha[idx] = e[idx] * inv
//   N4 <= idx < N4+P4 : pooled = g_pool*inv, g_pool reset
// Fence-free g_sum reset via last-block ticket (entry-read + __syncthreads).
__global__ void __launch_bounds__(256) k_fin(float* __restrict__ pooled,
                                             float* __restrict__ alpha, int N4) {
    const float inv = 1.0f / g_sum;     // read before any reset can happen
    __syncthreads();                    // all threads in this block have read

    const int idx = blockIdx.x * blockDim.x + threadIdx.x;
    const int P4 = (G_SEG * C) / 4;

    if (idx < N4) {
        float4 e = reinterpret_cast<const float4*>(g_exps)[idx];
        reinterpret_cast<float4*>(alpha)[idx] =
            make_float4(e.x * inv, e.y * inv, e.z * inv, e.w * inv);
    } else if (idx < N4 + P4) {
        int j = idx - N4;
        float4 v = reinterpret_cast<float4*>(g_pool)[j];
        reinterpret_cast<float4*>(pooled)[j] =
            make_float4(v.x * inv, v.y * inv, v.z * inv, v.w * inv);
        reinterpret_cast<float4*>(g_pool)[j] = make_float4(0.f, 0.f, 0.f, 0.f);
    }

    if (threadIdx.x == 0) {
        unsigned int t = atomicAdd(&g_fin_count, 1u);
        if (t == gridDim.x - 1) {
            g_sum = 0.0f;
            g_fin_count = 0u;
        }
    }
}

extern "C" void kernel_launch(void* const* d_in, const int* in_sizes, int n_in,
                              void* d_out, int out_size) {
    // Defensive input mapping by element counts: x: N*C, W: C, b: 1, batch: N
    const float* x = nullptr;
    const float* W = nullptr;
    const float* b = nullptr;
    const int*   batch = nullptr;
    int N = 0;
    {
        int xi = 0;
        for (int i = 1; i < n_in; i++) if (in_sizes[i] > in_sizes[xi]) xi = i;
        x = (const float*)d_in[xi];
        N = in_sizes[xi] / C;
        for (int i = 0; i < n_in; i++) {
            if (i == xi) continue;
            if (in_sizes[i] == C)      W = (const float*)d_in[i];
            else if (in_sizes[i] == 1) b = (const float*)d_in[i];
            else if (in_sizes[i] == N) batch = (const int*)d_in[i];
        }
    }

    float* pooled = (float*)d_out;             // [G_SEG, C]
    float* alpha  = (float*)d_out + G_SEG * C; // [N]

    int nwarps  = (N + RPW - 1) / RPW;
    int nblocks = (nwarps + 7) / 8;            // 8 warps (256 thr) per block
    k_main<<<nblocks, 256>>>(x, W, b, batch, N);

    int N4  = N / 4;
    int tot = N4 + (G_SEG * C) / 4;
    k_fin<<<(tot + 255) / 256, 256>>>(pooled, alpha, N4);
}

// round 16
// speedup vs baseline: 1.1428x; 1.0440x over previous
#include <cuda_runtime.h>

#define C 128
#define G_SEG 1024
#define MAX_N 1000000
#define RPW 32       // rows per warp — measured minimum (128/64/32/16 -> ~93/92.9/90.8/98.9)
#define TPB 128      // k_main threads per block: 4 warps (finer block granularity)

// Scratch (zero-initialized at module load; zero-invariant restored every replay)
static __device__ float g_exps[MAX_N];        // e_i (unnormalized), fully overwritten
static __device__ float g_pool[G_SEG * C];    // unnormalized pooled sums (reset by k_fin)
static __device__ float g_sum;                // softmax denominator (reset by k_fin last block)
static __device__ unsigned int g_fin_count;   // k_fin completion counter (reset by last block)

__device__ __forceinline__ void flush_acc(int seg, int lane, float4& acc) {
    int gc = min(max(seg, 0), G_SEG - 1);
    float* p = g_pool + gc * C + lane * 4;
    atomicAdd(p + 0, acc.x);
    atomicAdd(p + 1, acc.y);
    atomicAdd(p + 2, acc.z);
    atomicAdd(p + 3, acc.w);
    acc = make_float4(0.f, 0.f, 0.f, 0.f);
}

// k_main: single 512 MB pass over x, 4 rows in flight per warp (MLP=4).
// Quad fast-path on sorted batch; fence-free; atomics into g_pool scratch.
// 4 warps/block: finer scheduling granularity, smaller block-retire skew.
__global__ void __launch_bounds__(TPB) k_main(const float* __restrict__ x,
                                              const float* __restrict__ W,
                                              const float* __restrict__ b,
                                              const int* __restrict__ batch,
                                              int N) {
    const int lane  = threadIdx.x & 31;
    const int gwarp = (blockIdx.x * blockDim.x + threadIdx.x) >> 5;
    const int start = gwarp * RPW;

    float lsum = 0.0f;   // warp-uniform

    if (start < N) {
        const int end = min(start + RPW, N);
        const float4 wv = __ldg(reinterpret_cast<const float4*>(W) + lane);
        const float  bb = __ldg(b);
        const float4* xv4 = reinterpret_cast<const float4*>(x);

        int cur = __ldg(batch + start);
        float4 acc = make_float4(0.f, 0.f, 0.f, 0.f);

        int i = start;
        for (; i + 3 < end; i += 4) {
            // 4 independent loads -> MLP=4 on the big stream
            float4 x0 = __ldg(xv4 + (size_t)(i + 0) * 32 + lane);
            float4 x1 = __ldg(xv4 + (size_t)(i + 1) * 32 + lane);
            float4 x2 = __ldg(xv4 + (size_t)(i + 2) * 32 + lane);
            float4 x3 = __ldg(xv4 + (size_t)(i + 3) * 32 + lane);
            int4   gq = __ldg(reinterpret_cast<const int4*>(batch + i)); // aligned

            float d0 = x0.x*wv.x + x0.y*wv.y + x0.z*wv.z + x0.w*wv.w;
            float d1 = x1.x*wv.x + x1.y*wv.y + x1.z*wv.z + x1.w*wv.w;
            float d2 = x2.x*wv.x + x2.y*wv.y + x2.z*wv.z + x2.w*wv.w;
            float d3 = x3.x*wv.x + x3.y*wv.y + x3.z*wv.z + x3.w*wv.w;

            // interleaved butterflies: 4 independent chains share the latency
            #pragma unroll
            for (int o = 16; o; o >>= 1) {
                d0 += __shfl_xor_sync(0xffffffffu, d0, o);
                d1 += __shfl_xor_sync(0xffffffffu, d1, o);
                d2 += __shfl_xor_sync(0xffffffffu, d2, o);
                d3 += __shfl_xor_sync(0xffffffffu, d3, o);
            }

            float e0 = __expf(d0 + bb);
            float e1 = __expf(d1 + bb);
            float e2 = __expf(d2 + bb);
            float e3 = __expf(d3 + bb);

            if (lane == 0)
                *reinterpret_cast<float4*>(g_exps + i) = make_float4(e0, e1, e2, e3);
            lsum += (e0 + e1) + (e2 + e3);

            if (gq.w == cur) {
                // fast path: whole quad in segment cur (sorted => all equal)
                acc.x = fmaf(e0, x0.x, acc.x); acc.y = fmaf(e0, x0.y, acc.y);
                acc.z = fmaf(e0, x0.z, acc.z); acc.w = fmaf(e0, x0.w, acc.w);
                acc.x = fmaf(e1, x1.x, acc.x); acc.y = fmaf(e1, x1.y, acc.y);
                acc.z = fmaf(e1, x1.z, acc.z); acc.w = fmaf(e1, x1.w, acc.w);
                acc.x = fmaf(e2, x2.x, acc.x); acc.y = fmaf(e2, x2.y, acc.y);
                acc.z = fmaf(e2, x2.z, acc.z); acc.w = fmaf(e2, x2.w, acc.w);
                acc.x = fmaf(e3, x3.x, acc.x); acc.y = fmaf(e3, x3.y, acc.y);
                acc.z = fmaf(e3, x3.z, acc.z); acc.w = fmaf(e3, x3.w, acc.w);
            } else {
                // slow path: at least one boundary inside the quad
                if (gq.x != cur) { flush_acc(cur, lane, acc); cur = gq.x; }
                acc.x = fmaf(e0, x0.x, acc.x); acc.y = fmaf(e0, x0.y, acc.y);
                acc.z = fmaf(e0, x0.z, acc.z); acc.w = fmaf(e0, x0.w, acc.w);

                if (gq.y != cur) { flush_acc(cur, lane, acc); cur = gq.y; }
                acc.x = fmaf(e1, x1.x, acc.x); acc.y = fmaf(e1, x1.y, acc.y);
                acc.z = fmaf(e1, x1.z, acc.z); acc.w = fmaf(e1, x1.w, acc.w);

                if (gq.z != cur) { flush_acc(cur, lane, acc); cur = gq.z; }
                acc.x = fmaf(e2, x2.x, acc.x); acc.y = fmaf(e2, x2.y, acc.y);
                acc.z = fmaf(e2, x2.z, acc.z); acc.w = fmaf(e2, x2.w, acc.w);

                if (gq.w != cur) { flush_acc(cur, lane, acc); cur = gq.w; }
                acc.x = fmaf(e3, x3.x, acc.x); acc.y = fmaf(e3, x3.y, acc.y);
                acc.z = fmaf(e3, x3.z, acc.z); acc.w = fmaf(e3, x3.w, acc.w);
            }
        }

        // generic tail (unused when chunk length % 4 == 0)
        for (; i < end; i++) {
            float4 xv = __ldg(xv4 + (size_t)i * 32 + lane);
            int g = __ldg(batch + i);
            float dd = xv.x*wv.x + xv.y*wv.y + xv.z*wv.z + xv.w*wv.w;
            #pragma unroll
            for (int o = 16; o; o >>= 1) dd += __shfl_xor_sync(0xffffffffu, dd, o);
            float ee = __expf(dd + bb);
            if (lane == 0) g_exps[i] = ee;
            lsum += ee;
            if (g != cur) { flush_acc(cur, lane, acc); cur = g; }
            acc.x = fmaf(ee, xv.x, acc.x); acc.y = fmaf(ee, xv.y, acc.y);
            acc.z = fmaf(ee, xv.z, acc.z); acc.w = fmaf(ee, xv.w, acc.w);
        }

        flush_acc(cur, lane, acc);
    }

    // block-level reduction of per-warp sums into g_sum (no fences)
    __shared__ float s_red[TPB / 32];
    if (lane == 0) s_red[threadIdx.x >> 5] = lsum;
    __syncthreads();
    if (threadIdx.x == 0) {
        float s = 0.0f;
        #pragma unroll
        for (int w = 0; w < TPB / 32; w++) s += s_red[w];
        atomicAdd(&g_sum, s);
    }
}

// k_fin: direct-indexed, one float4 op per thread (measured-best form).
//   idx < N4          : alpha[idx] = e[idx] * inv
//   N4 <= idx < N4+P4 : pooled = g_pool*inv, g_pool reset
// Fence-free g_sum reset via last-block ticket (entry-read + __syncthreads).
__global__ void __launch_bounds__(256) k_fin(float* __restrict__ pooled,
                                             float* __restrict__ alpha, int N4) {
    const float inv = 1.0f / g_sum;     // read before any reset can happen
    __syncthreads();                    // all threads in this block have read

    const int idx = blockIdx.x * blockDim.x + threadIdx.x;
    const int P4 = (G_SEG * C) / 4;

    if (idx < N4) {
        float4 e = reinterpret_cast<const float4*>(g_exps)[idx];
        reinterpret_cast<float4*>(alpha)[idx] =
            make_float4(e.x * inv, e.y * inv, e.z * inv, e.w * inv);
    } else if (idx < N4 + P4) {
        int j = idx - N4;
        float4 v = reinterpret_cast<float4*>(g_pool)[j];
        reinterpret_cast<float4*>(pooled)[j] =
            make_float4(v.x * inv, v.y * inv, v.z * inv, v.w * inv);
        reinterpret_cast<float4*>(g_pool)[j] = make_float4(0.f, 0.f, 0.f, 0.f);
    }

    if (threadIdx.x == 0) {
        unsigned int t = atomicAdd(&g_fin_count, 1u);
        if (t == gridDim.x - 1) {
            g_sum = 0.0f;
            g_fin_count = 0u;
        }
    }
}

extern "C" void kernel_launch(void* const* d_in, const int* in_sizes, int n_in,
                              void* d_out, int out_size) {
    // Defensive input mapping by element counts: x: N*C, W: C, b: 1, batch: N
    const float* x = nullptr;
    const float* W = nullptr;
    const float* b = nullptr;
    const int*   batch = nullptr;
    int N = 0;
    {
        int xi = 0;
        for (int i = 1; i < n_in; i++) if (in_sizes[i] > in_sizes[xi]) xi = i;
        x = (const float*)d_in[xi];
        N = in_sizes[xi] / C;
        for (int i = 0; i < n_in; i++) {
            if (i == xi) continue;
            if (in_sizes[i] == C)      W = (const float*)d_in[i];
            else if (in_sizes[i] == 1) b = (const float*)d_in[i];
            else if (in_sizes[i] == N) batch = (const int*)d_in[i];
        }
    }

    float* pooled = (float*)d_out;             // [G_SEG, C]
    float* alpha  = (float*)d_out + G_SEG * C; // [N]

    int nwarps  = (N + RPW - 1) / RPW;
    int nblocks = (nwarps + (TPB / 32) - 1) / (TPB / 32);
    k_main<<<nblocks, TPB>>>(x, W, b, batch, N);

    int N4  = N / 4;
    int tot = N4 + (G_SEG * C) / 4;
    k_fin<<<(tot + 255) / 256, 256>>>(pooled, alpha, N4);
}

// round 17
// speedup vs baseline: 1.1483x; 1.0048x over previous
#include <cuda_runtime.h>

#define C 128
#define G_SEG 1024
#define MAX_N 1000000
#define RPW 32       // rows per warp — measured minimum (128/64/32/16 -> ~93/92.9/90.8/98.9)
#define TPB 64       // k_main threads per block: 2 warps (TPB curve: 256->128 gave -3.8us)

// Scratch (zero-initialized at module load; zero-invariant restored every replay)
static __device__ float g_exps[MAX_N];        // e_i (unnormalized), fully overwritten
static __device__ float g_pool[G_SEG * C];    // unnormalized pooled sums (reset by k_fin)
static __device__ float g_sum;                // softmax denominator (reset by k_fin last block)
static __device__ unsigned int g_fin_count;   // k_fin completion counter (reset by last block)

__device__ __forceinline__ void flush_acc(int seg, int lane, float4& acc) {
    int gc = min(max(seg, 0), G_SEG - 1);
    float* p = g_pool + gc * C + lane * 4;
    atomicAdd(p + 0, acc.x);
    atomicAdd(p + 1, acc.y);
    atomicAdd(p + 2, acc.z);
    atomicAdd(p + 3, acc.w);
    acc = make_float4(0.f, 0.f, 0.f, 0.f);
}

// k_main: single 512 MB pass over x, 4 rows in flight per warp (MLP=4).
// Quad fast-path on sorted batch; fence-free; atomics into g_pool scratch.
// 2 warps/block: finest block granularity (gradient has paid twice).
__global__ void __launch_bounds__(TPB) k_main(const float* __restrict__ x,
                                              const float* __restrict__ W,
                                              const float* __restrict__ b,
                                              const int* __restrict__ batch,
                                              int N) {
    const int lane  = threadIdx.x & 31;
    const int gwarp = (blockIdx.x * blockDim.x + threadIdx.x) >> 5;
    const int start = gwarp * RPW;

    float lsum = 0.0f;   // warp-uniform

    if (start < N) {
        const int end = min(start + RPW, N);
        const float4 wv = __ldg(reinterpret_cast<const float4*>(W) + lane);
        const float  bb = __ldg(b);
        const float4* xv4 = reinterpret_cast<const float4*>(x);

        int cur = __ldg(batch + start);
        float4 acc = make_float4(0.f, 0.f, 0.f, 0.f);

        int i = start;
        for (; i + 3 < end; i += 4) {
            // 4 independent loads -> MLP=4 on the big stream
            float4 x0 = __ldg(xv4 + (size_t)(i + 0) * 32 + lane);
            float4 x1 = __ldg(xv4 + (size_t)(i + 1) * 32 + lane);
            float4 x2 = __ldg(xv4 + (size_t)(i + 2) * 32 + lane);
            float4 x3 = __ldg(xv4 + (size_t)(i + 3) * 32 + lane);
            int4   gq = __ldg(reinterpret_cast<const int4*>(batch + i)); // aligned

            float d0 = x0.x*wv.x + x0.y*wv.y + x0.z*wv.z + x0.w*wv.w;
            float d1 = x1.x*wv.x + x1.y*wv.y + x1.z*wv.z + x1.w*wv.w;
            float d2 = x2.x*wv.x + x2.y*wv.y + x2.z*wv.z + x2.w*wv.w;
            float d3 = x3.x*wv.x + x3.y*wv.y + x3.z*wv.z + x3.w*wv.w;

            // interleaved butterflies: 4 independent chains share the latency
            #pragma unroll
            for (int o = 16; o; o >>= 1) {
                d0 += __shfl_xor_sync(0xffffffffu, d0, o);
                d1 += __shfl_xor_sync(0xffffffffu, d1, o);
                d2 += __shfl_xor_sync(0xffffffffu, d2, o);
                d3 += __shfl_xor_sync(0xffffffffu, d3, o);
            }

            float e0 = __expf(d0 + bb);
            float e1 = __expf(d1 + bb);
            float e2 = __expf(d2 + bb);
            float e3 = __expf(d3 + bb);

            if (lane == 0)
                *reinterpret_cast<float4*>(g_exps + i) = make_float4(e0, e1, e2, e3);
            lsum += (e0 + e1) + (e2 + e3);

            if (gq.w == cur) {
                // fast path: whole quad in segment cur (sorted => all equal)
                acc.x = fmaf(e0, x0.x, acc.x); acc.y = fmaf(e0, x0.y, acc.y);
                acc.z = fmaf(e0, x0.z, acc.z); acc.w = fmaf(e0, x0.w, acc.w);
                acc.x = fmaf(e1, x1.x, acc.x); acc.y = fmaf(e1, x1.y, acc.y);
                acc.z = fmaf(e1, x1.z, acc.z); acc.w = fmaf(e1, x1.w, acc.w);
                acc.x = fmaf(e2, x2.x, acc.x); acc.y = fmaf(e2, x2.y, acc.y);
                acc.z = fmaf(e2, x2.z, acc.z); acc.w = fmaf(e2, x2.w, acc.w);
                acc.x = fmaf(e3, x3.x, acc.x); acc.y = fmaf(e3, x3.y, acc.y);
                acc.z = fmaf(e3, x3.z, acc.z); acc.w = fmaf(e3, x3.w, acc.w);
            } else {
                // slow path: at least one boundary inside the quad
                if (gq.x != cur) { flush_acc(cur, lane, acc); cur = gq.x; }
                acc.x = fmaf(e0, x0.x, acc.x); acc.y = fmaf(e0, x0.y, acc.y);
                acc.z = fmaf(e0, x0.z, acc.z); acc.w = fmaf(e0, x0.w, acc.w);

                if (gq.y != cur) { flush_acc(cur, lane, acc); cur = gq.y; }
                acc.x = fmaf(e1, x1.x, acc.x); acc.y = fmaf(e1, x1.y, acc.y);
                acc.z = fmaf(e1, x1.z, acc.z); acc.w = fmaf(e1, x1.w, acc.w);

                if (gq.z != cur) { flush_acc(cur, lane, acc); cur = gq.z; }
                acc.x = fmaf(e2, x2.x, acc.x); acc.y = fmaf(e2, x2.y, acc.y);
                acc.z = fmaf(e2, x2.z, acc.z); acc.w = fmaf(e2, x2.w, acc.w);

                if (gq.w != cur) { flush_acc(cur, lane, acc); cur = gq.w; }
                acc.x = fmaf(e3, x3.x, acc.x); acc.y = fmaf(e3, x3.y, acc.y);
                acc.z = fmaf(e3, x3.z, acc.z); acc.w = fmaf(e3, x3.w, acc.w);
            }
        }

        // generic tail (unused when chunk length % 4 == 0)
        for (; i < end; i++) {
            float4 xv = __ldg(xv4 + (size_t)i * 32 + lane);
            int g = __ldg(batch + i);
            float dd = xv.x*wv.x + xv.y*wv.y + xv.z*wv.z + xv.w*wv.w;
            #pragma unroll
            for (int o = 16; o; o >>= 1) dd += __shfl_xor_sync(0xffffffffu, dd, o);
            float ee = __expf(dd + bb);
            if (lane == 0) g_exps[i] = ee;
            lsum += ee;
            if (g != cur) { flush_acc(cur, lane, acc); cur = g; }
            acc.x = fmaf(ee, xv.x, acc.x); acc.y = fmaf(ee, xv.y, acc.y);
            acc.z = fmaf(ee, xv.z, acc.z); acc.w = fmaf(ee, xv.w, acc.w);
        }

        flush_acc(cur, lane, acc);
    }

    // block-level reduction of per-warp sums into g_sum (no fences)
    __shared__ float s_red[TPB / 32];
    if (lane == 0) s_red[threadIdx.x >> 5] = lsum;
    __syncthreads();
    if (threadIdx.x == 0) {
        float s = 0.0f;
        #pragma unroll
        for (int w = 0; w < TPB / 32; w++) s += s_red[w];
        atomicAdd(&g_sum, s);
    }
}

// k_fin: direct-indexed, one float4 op per thread (measured-best form).
//   idx < N4          : alpha[idx] = e[idx] * inv
//   N4 <= idx < N4+P4 : pooled = g_pool*inv, g_pool reset
// Fence-free g_sum reset via last-block ticket (entry-read + __syncthreads).
__global__ void __launch_bounds__(256) k_fin(float* __restrict__ pooled,
                                             float* __restrict__ alpha, int N4) {
    const float inv = 1.0f / g_sum;     // read before any reset can happen
    __syncthreads();                    // all threads in this block have read

    const int idx = blockIdx.x * blockDim.x + threadIdx.x;
    const int P4 = (G_SEG * C) / 4;

    if (idx < N4) {
        float4 e = reinterpret_cast<const float4*>(g_exps)[idx];
        reinterpret_cast<float4*>(alpha)[idx] =
            make_float4(e.x * inv, e.y * inv, e.z * inv, e.w * inv);
    } else if (idx < N4 + P4) {
        int j = idx - N4;
        float4 v = reinterpret_cast<float4*>(g_pool)[j];
        reinterpret_cast<float4*>(pooled)[j] =
            make_float4(v.x * inv, v.y * inv, v.z * inv, v.w * inv);
        reinterpret_cast<float4*>(g_pool)[j] = make_float4(0.f, 0.f, 0.f, 0.f);
    }

    if (threadIdx.x == 0) {
        unsigned int t = atomicAdd(&g_fin_count, 1u);
        if (t == gridDim.x - 1) {
            g_sum = 0.0f;
            g_fin_count = 0u;
        }
    }
}

extern "C" void kernel_launch(void* const* d_in, const int* in_sizes, int n_in,
                              void* d_out, int out_size) {
    // Defensive input mapping by element counts: x: N*C, W: C, b: 1, batch: N
    const float* x = nullptr;
    const float* W = nullptr;
    const float* b = nullptr;
    const int*   batch = nullptr;
    int N = 0;
    {
        int xi = 0;
        for (int i = 1; i < n_in; i++) if (in_sizes[i] > in_sizes[xi]) xi = i;
        x = (const float*)d_in[xi];
        N = in_sizes[xi] / C;
        for (int i = 0; i < n_in; i++) {
            if (i == xi) continue;
            if (in_sizes[i] == C)      W = (const float*)d_in[i];
            else if (in_sizes[i] == 1) b = (const float*)d_in[i];
            else if (in_sizes[i] == N) batch = (const int*)d_in[i];
        }
    }

    float* pooled = (float*)d_out;             // [G_SEG, C]
    float* alpha  = (float*)d_out + G_SEG * C; // [N]

    int nwarps  = (N + RPW - 1) / RPW;
    int nblocks = (nwarps + (TPB / 32) - 1) / (TPB / 32);
    k_main<<<nblocks, TPB>>>(x, W, b, batch, N);

    int N4  = N / 4;
    int tot = N4 + (G_SEG * C) / 4;
    k_fin<<<(tot + 255) / 256, 256>>>(pooled, alpha, N4);
}